// round 8
// baseline (speedup 1.0000x reference)
#include <cuda_runtime.h>

// HaversineSmoothedLoss — packed-f32x2 main kernel.
//   a  = (1 - u1·u2)/2            (unit 3-vectors; no per-pair trig)
//   w  = exp2( sqrt(|a|) * Q(a) ) Q = K*log2(e)*asin-series; far cells underflow to 0
//   loss_b = log(Z_b) - (Σ w·x)/S_b ,  Z = Σ e^x, S = Σ w
//
// K1: 512 blocks (256 thr) = 128 row-groups (4 rows) × 4 chunks (8192 cells).
// Dot product, asin-poly, and muls packed 2-wide via fma.rn.f32x2 / mul.rn.f32x2
// (sm_103a packed fp32 pipe — unreachable from plain C++). MUFU ops stay scalar.

#define C_CELLS 32768
#define B_ROWS  512
#define RPB     4
#define SPLIT   4
#define CHUNK   (C_CELLS / SPLIT)          // 8192
#define THREADS 256
#define NWARPS  (THREADS / 32)             // 8
#define ITERS   (CHUNK / (4 * THREADS))    // 8
#define GRID    ((B_ROWS / RPB) * SPLIT)   // 512

typedef unsigned long long u64;

__device__ float d_ux[C_CELLS];
__device__ float d_uy[C_CELLS];
__device__ float d_uz[C_CELLS];
__device__ float d_prow[3][B_ROWS];        // -0.5 * row unit vectors
__device__ float d_pZ[B_ROWS * SPLIT];
__device__ float d_pS[B_ROWS * SPLIT];
__device__ float d_pW[B_ROWS * SPLIT];
__device__ unsigned int d_ctr = 0;

__device__ __forceinline__ float fsqrt_ap(float a) {
    float r; asm("sqrt.approx.f32 %0, %1;" : "=f"(r) : "f"(a)); return r;
}
__device__ __forceinline__ float fexp2_ap(float a) {
    float r; asm("ex2.approx.f32 %0, %1;" : "=f"(r) : "f"(a)); return r;
}
__device__ __forceinline__ u64 pk2(float lo, float hi) {
    u64 r; asm("mov.b64 %0, {%1, %2};" : "=l"(r) : "f"(lo), "f"(hi)); return r;
}
__device__ __forceinline__ void upk2(float& lo, float& hi, u64 v) {
    asm("mov.b64 {%0, %1}, %2;" : "=f"(lo), "=f"(hi) : "l"(v));
}
__device__ __forceinline__ u64 fma2(u64 a, u64 b, u64 c) {
    u64 r; asm("fma.rn.f32x2 %0, %1, %2, %3;" : "=l"(r) : "l"(a), "l"(b), "l"(c)); return r;
}
__device__ __forceinline__ u64 mul2(u64 a, u64 b) {
    u64 r; asm("mul.rn.f32x2 %0, %1, %2;" : "=l"(r) : "l"(a), "l"(b)); return r;
}

__global__ void precompute(const float* __restrict__ geo,
                           const float* __restrict__ latlon) {
    const float d2r = 0.017453292519943295f;
    int i = blockIdx.x * blockDim.x + threadIdx.x;
    if (i < C_CELLS) {
        float lat = geo[2 * i]     * d2r;
        float lon = geo[2 * i + 1] * d2r;
        float sl, cl, so, co;
        sincosf(lat, &sl, &cl);
        sincosf(lon, &so, &co);
        d_ux[i] = sl;
        d_uy[i] = cl * so;
        d_uz[i] = cl * co;
    }
    if (i < B_ROWS) {
        float lat = latlon[2 * i]     * d2r;
        float lon = latlon[2 * i + 1] * d2r;
        float sl, cl, so, co;
        sincosf(lat, &sl, &cl);
        sincosf(lon, &so, &co);
        d_prow[0][i] = -0.5f * sl;
        d_prow[1][i] = -0.5f * cl * so;
        d_prow[2][i] = -0.5f * cl * co;
    }
}

__global__ __launch_bounds__(THREADS, 3)
void main_kernel(const float* __restrict__ logits,
                 float* __restrict__ out) {
    const int bx    = blockIdx.x;
    const int rg    = bx >> 2;             // row group 0..127
    const int ch    = bx & (SPLIT - 1);    // chunk 0..3
    const int row0  = rg * RPB;
    const int tid   = threadIdx.x;
    const int qbase = (ch * CHUNK) >> 2;   // float4 quad base of this chunk

    // Packed constants.
    const u64 HALF2  = pk2(0.5f, 0.5f);
    const u64 KL_2   = pk2(-245.104328f, -245.104328f);   // -(2*6371/75)*log2(e)
    const u64 KL3_2  = pk2(-40.8507213f, -40.8507213f);
    const u64 KL5_2  = pk2(-18.3828246f, -18.3828246f);
    const u64 KL7_2  = pk2(-10.9421575f, -10.9421575f);
    const u64 L2E_2  = pk2(1.4426950408889634f, 1.4426950408889634f);

    // Row normals packed-broadcast (hoisted: uniform per block).
    u64 nx2[RPB], ny2[RPB], nz2[RPB];
    #pragma unroll
    for (int r = 0; r < RPB; r++) {
        float a0 = d_prow[0][row0 + r];
        float a1 = d_prow[1][row0 + r];
        float a2 = d_prow[2][row0 + r];
        nx2[r] = pk2(a0, a0); ny2[r] = pk2(a1, a1); nz2[r] = pk2(a2, a2);
    }

    const float4* __restrict__ lg4 = (const float4*)logits;
    const float4* __restrict__ ux4 = (const float4*)d_ux;
    const float4* __restrict__ uy4 = (const float4*)d_uy;
    const float4* __restrict__ uz4 = (const float4*)d_uz;

    float Z[RPB], S[RPB], WX[RPB];
    #pragma unroll
    for (int r = 0; r < RPB; r++) { Z[r] = 0.f; S[r] = 0.f; WX[r] = 0.f; }

    #pragma unroll 1
    for (int it = 0; it < ITERS; it++) {
        const int q = qbase + it * THREADS + tid;

        // Front-batch all 7 LDG.128.
        float4 xr[RPB];
        #pragma unroll
        for (int r = 0; r < RPB; r++)
            xr[r] = __ldg(lg4 + (size_t)(row0 + r) * (C_CELLS / 4) + q);
        const float4 gx = __ldg(ux4 + q);
        const float4 gy = __ldg(uy4 + q);
        const float4 gz = __ldg(uz4 + q);

        // Celltab packed pairs (lo,hi) for cells {0,1} and {2,3}.
        const u64 gx2[2] = {pk2(gx.x, gx.y), pk2(gx.z, gx.w)};
        const u64 gy2[2] = {pk2(gy.x, gy.y), pk2(gy.z, gy.w)};
        const u64 gz2[2] = {pk2(gz.x, gz.y), pk2(gz.z, gz.w)};

        #pragma unroll
        for (int r = 0; r < RPB; r++) {
            const float xs[4] = {xr[r].x, xr[r].y, xr[r].z, xr[r].w};
            #pragma unroll
            for (int p = 0; p < 2; p++) {
                const float x0 = xs[2 * p], x1 = xs[2 * p + 1];
                const u64 x2v = pk2(x0, x1);

                // Z: packed mul, scalar EX2.
                u64 zx2 = mul2(x2v, L2E_2);
                float z0, z1; upk2(z0, z1, zx2);
                Z[r] += fexp2_ap(z0);
                Z[r] += fexp2_ap(z1);

                // a = 0.5 - 0.5*u1.u2 (packed dot).
                u64 a2 = fma2(nx2[r], gx2[p],
                         fma2(ny2[r], gy2[p],
                         fma2(nz2[r], gz2[p], HALF2)));
                // Q(a) packed poly.
                u64 q2 = fma2(a2, fma2(a2, fma2(a2, KL7_2, KL5_2), KL3_2), KL_2);

                float a0, a1; upk2(a0, a1, a2);
                float s0 = fsqrt_ap(fabsf(a0));
                float s1 = fsqrt_ap(fabsf(a1));
                u64 e2 = mul2(pk2(s0, s1), q2);
                float e0, e1; upk2(e0, e1, e2);
                float w0 = fexp2_ap(e0);           // underflow -> 0 for far cells
                float w1 = fexp2_ap(e1);

                S[r]  += w0 + w1;
                WX[r]  = fmaf(w0, x0, WX[r]);
                WX[r]  = fmaf(w1, x1, WX[r]);
            }
        }
    }

    // ---- Block reduction of 12 accumulators (deterministic tree) ----
    float acc[3 * RPB];
    #pragma unroll
    for (int r = 0; r < RPB; r++) {
        acc[r * 3 + 0] = Z[r]; acc[r * 3 + 1] = S[r]; acc[r * 3 + 2] = WX[r];
    }
    __shared__ float red[3 * RPB][NWARPS];
    const int lane = tid & 31, warp = tid >> 5;
    #pragma unroll
    for (int i = 0; i < 3 * RPB; i++) {
        float vv = acc[i];
        #pragma unroll
        for (int o = 16; o > 0; o >>= 1) vv += __shfl_down_sync(0xffffffffu, vv, o);
        if (lane == 0) red[i][warp] = vv;
    }
    __syncthreads();
    if (tid < 3 * RPB) {
        float vv = 0.f;
        #pragma unroll
        for (int wi = 0; wi < NWARPS; wi++) vv += red[tid][wi];
        const int r     = tid / 3;
        const int which = tid % 3;
        const int idx   = (row0 + r) * SPLIT + ch;
        if      (which == 0) d_pZ[idx] = vv;
        else if (which == 1) d_pS[idx] = vv;
        else                 d_pW[idx] = vv;
    }

    // ---- Last block reduces everything ----
    __shared__ bool isLast;
    __syncthreads();
    if (tid == 0) {
        __threadfence();
        unsigned int t = atomicAdd(&d_ctr, 1u);
        isLast = (t == (unsigned int)(GRID - 1));
    }
    __syncthreads();

    if (isLast) {
        float v = 0.f;
        #pragma unroll
        for (int half = 0; half < B_ROWS / THREADS; half++) {   // 2 rows/thread
            const int b = tid + half * THREADS;
            float Zt = 0.f, St = 0.f, Wt = 0.f;
            #pragma unroll
            for (int cc = 0; cc < SPLIT; cc++) {
                Zt += __ldcg(&d_pZ[b * SPLIT + cc]);
                St += __ldcg(&d_pS[b * SPLIT + cc]);
                Wt += __ldcg(&d_pW[b * SPLIT + cc]);
            }
            v += logf(Zt) - Wt * __fdividef(1.0f, St);
        }
        __shared__ float fin[NWARPS];
        #pragma unroll
        for (int o = 16; o > 0; o >>= 1) v += __shfl_down_sync(0xffffffffu, v, o);
        if (lane == 0) fin[warp] = v;
        __syncthreads();
        if (tid == 0) {
            float s = 0.f;
            #pragma unroll
            for (int i = 0; i < NWARPS; i++) s += fin[i];
            out[0] = s * (1.0f / (float)B_ROWS);
            d_ctr  = 0;   // reset for graph replay
        }
    }
}

extern "C" void kernel_launch(void* const* d_in, const int* in_sizes, int n_in,
                              void* d_out, int out_size) {
    const float* logits = (const float*)d_in[0];   // [512, 32768]
    const float* latlon = (const float*)d_in[1];   // [512, 2]
    const float* geo    = (const float*)d_in[2];   // [32768, 2]

    precompute<<<(C_CELLS + 255) / 256, 256>>>(geo, latlon);
    main_kernel<<<GRID, THREADS>>>(logits, (float*)d_out);
}

// round 9
// speedup vs baseline: 1.0129x; 1.0129x over previous
#include <cuda_runtime.h>

// HaversineSmoothedLoss — R7 structure + instruction diet.
//   a  = (1 - u1·u2)/2             (unit 3-vectors; no per-pair trig)
//   w  = exp2( sqrt(|a|) * (KL + KL3*a) )   1-term asin correction:
//        truncation error < 1.3e-5 on weight-relevant cells (a < 0.004)
//   loss_b = log(Z_b) - (Σ w·x)/S_b ,  Z = Σ e^x, S = Σ w
//
// K0: celltab unit vectors (once).
// K1: 512 blocks (256 thr) = 128 row-groups (4 rows) × 4 chunks (8192 cells).
//     8 iters/thread, 7 front-batched LDG.128 per iter, branchless 12-inst/elem loop.
//     Last block (arrival counter) reduces partials to the loss.

#define C_CELLS 32768
#define B_ROWS  512
#define RPB     4
#define SPLIT   4
#define CHUNK   (C_CELLS / SPLIT)          // 8192
#define THREADS 256
#define NWARPS  (THREADS / 32)             // 8
#define ITERS   (CHUNK / (4 * THREADS))    // 8
#define GRID    ((B_ROWS / RPB) * SPLIT)   // 512

__device__ float d_ux[C_CELLS];
__device__ float d_uy[C_CELLS];
__device__ float d_uz[C_CELLS];
__device__ float d_prow[3][B_ROWS];        // -0.5 * row unit vectors
__device__ float d_pZ[B_ROWS * SPLIT];
__device__ float d_pS[B_ROWS * SPLIT];
__device__ float d_pW[B_ROWS * SPLIT];
__device__ unsigned int d_ctr = 0;

__device__ __forceinline__ float fsqrt_ap(float a) {
    float r; asm("sqrt.approx.f32 %0, %1;" : "=f"(r) : "f"(a)); return r;
}
__device__ __forceinline__ float fexp2_ap(float a) {
    float r; asm("ex2.approx.f32 %0, %1;" : "=f"(r) : "f"(a)); return r;
}

__global__ void precompute(const float* __restrict__ geo,
                           const float* __restrict__ latlon) {
    const float d2r = 0.017453292519943295f;
    int i = blockIdx.x * blockDim.x + threadIdx.x;
    if (i < C_CELLS) {
        float lat = geo[2 * i]     * d2r;
        float lon = geo[2 * i + 1] * d2r;
        float sl, cl, so, co;
        sincosf(lat, &sl, &cl);
        sincosf(lon, &so, &co);
        d_ux[i] = sl;
        d_uy[i] = cl * so;
        d_uz[i] = cl * co;
    }
    if (i < B_ROWS) {
        float lat = latlon[2 * i]     * d2r;
        float lon = latlon[2 * i + 1] * d2r;
        float sl, cl, so, co;
        sincosf(lat, &sl, &cl);
        sincosf(lon, &so, &co);
        d_prow[0][i] = -0.5f * sl;
        d_prow[1][i] = -0.5f * cl * so;
        d_prow[2][i] = -0.5f * cl * co;
    }
}

__global__ __launch_bounds__(THREADS, 4)
void main_kernel(const float* __restrict__ logits,
                 float* __restrict__ out) {
    const int bx    = blockIdx.x;
    const int rg    = bx >> 2;             // row group 0..127
    const int ch    = bx & (SPLIT - 1);    // chunk 0..3
    const int row0  = rg * RPB;
    const int tid   = threadIdx.x;
    const int qbase = (ch * CHUNK) >> 2;   // float4 quad base of this chunk

    const float LOG2E = 1.4426950408889634f;
    const float KL  = -245.104328f;        // -(2*6371/75)*log2(e)
    const float KL3 = -40.8507213f;        // KL/6   (imm multiplier -> FFMA-imm, rt 1)

    // Row uniforms (block-uniform loads).
    float nx[RPB], ny[RPB], nz[RPB];
    #pragma unroll
    for (int r = 0; r < RPB; r++) {
        nx[r] = d_prow[0][row0 + r];
        ny[r] = d_prow[1][row0 + r];
        nz[r] = d_prow[2][row0 + r];
    }

    const float4* __restrict__ lg4 = (const float4*)logits;
    const float4* __restrict__ ux4 = (const float4*)d_ux;
    const float4* __restrict__ uy4 = (const float4*)d_uy;
    const float4* __restrict__ uz4 = (const float4*)d_uz;

    float Z[RPB], S[RPB], WX[RPB];
    #pragma unroll
    for (int r = 0; r < RPB; r++) { Z[r] = 0.f; S[r] = 0.f; WX[r] = 0.f; }

    #pragma unroll 1
    for (int it = 0; it < ITERS; it++) {
        const int q = qbase + it * THREADS + tid;

        // Front-batch all 7 LDG.128 for this iteration.
        float4 xr[RPB];
        #pragma unroll
        for (int r = 0; r < RPB; r++)
            xr[r] = __ldg(lg4 + (size_t)(row0 + r) * (C_CELLS / 4) + q);
        const float4 gx = __ldg(ux4 + q);
        const float4 gy = __ldg(uy4 + q);
        const float4 gz = __ldg(uz4 + q);

        const float gxs[4] = {gx.x, gx.y, gx.z, gx.w};
        const float gys[4] = {gy.x, gy.y, gy.z, gy.w};
        const float gzs[4] = {gz.x, gz.y, gz.z, gz.w};

        #pragma unroll
        for (int r = 0; r < RPB; r++) {
            const float xs[4] = {xr[r].x, xr[r].y, xr[r].z, xr[r].w};
            #pragma unroll
            for (int k = 0; k < 4; k++) {
                const float x = xs[k];
                Z[r] += fexp2_ap(x * LOG2E);
                float a = fmaf(nx[r], gxs[k], fmaf(ny[r], gys[k], fmaf(nz[r], gzs[k], 0.5f)));
                float s  = fsqrt_ap(fabsf(a));       // |a|: free operand modifier
                float qq = fmaf(a, KL3, KL);         // 1-term asin correction (FFMA-imm)
                float w  = fexp2_ap(s * qq);         // underflows to 0 for far cells
                S[r]  += w;
                WX[r]  = fmaf(w, x, WX[r]);
            }
        }
    }

    // ---- Block reduction of 12 accumulators (deterministic tree) ----
    float acc[3 * RPB];
    #pragma unroll
    for (int r = 0; r < RPB; r++) {
        acc[r * 3 + 0] = Z[r]; acc[r * 3 + 1] = S[r]; acc[r * 3 + 2] = WX[r];
    }
    __shared__ float red[3 * RPB][NWARPS];
    const int lane = tid & 31, warp = tid >> 5;
    #pragma unroll
    for (int i = 0; i < 3 * RPB; i++) {
        float vv = acc[i];
        #pragma unroll
        for (int o = 16; o > 0; o >>= 1) vv += __shfl_down_sync(0xffffffffu, vv, o);
        if (lane == 0) red[i][warp] = vv;
    }
    __syncthreads();
    if (tid < 3 * RPB) {
        float vv = 0.f;
        #pragma unroll
        for (int wi = 0; wi < NWARPS; wi++) vv += red[tid][wi];
        const int r     = tid / 3;
        const int which = tid % 3;
        const int idx   = (row0 + r) * SPLIT + ch;
        if      (which == 0) d_pZ[idx] = vv;
        else if (which == 1) d_pS[idx] = vv;
        else                 d_pW[idx] = vv;
    }

    // ---- Last block reduces everything ----
    __shared__ bool isLast;
    __syncthreads();
    if (tid == 0) {
        __threadfence();
        unsigned int t = atomicAdd(&d_ctr, 1u);
        isLast = (t == (unsigned int)(GRID - 1));
    }
    __syncthreads();

    if (isLast) {
        float v = 0.f;
        #pragma unroll
        for (int half = 0; half < B_ROWS / THREADS; half++) {   // 2 rows/thread
            const int b = tid + half * THREADS;
            float Zt = 0.f, St = 0.f, Wt = 0.f;
            #pragma unroll
            for (int cc = 0; cc < SPLIT; cc++) {
                Zt += __ldcg(&d_pZ[b * SPLIT + cc]);
                St += __ldcg(&d_pS[b * SPLIT + cc]);
                Wt += __ldcg(&d_pW[b * SPLIT + cc]);
            }
            v += logf(Zt) - Wt * __fdividef(1.0f, St);
        }
        __shared__ float fin[NWARPS];
        #pragma unroll
        for (int o = 16; o > 0; o >>= 1) v += __shfl_down_sync(0xffffffffu, v, o);
        if (lane == 0) fin[warp] = v;
        __syncthreads();
        if (tid == 0) {
            float s = 0.f;
            #pragma unroll
            for (int i = 0; i < NWARPS; i++) s += fin[i];
            out[0] = s * (1.0f / (float)B_ROWS);
            d_ctr  = 0;   // reset for graph replay
        }
    }
}

extern "C" void kernel_launch(void* const* d_in, const int* in_sizes, int n_in,
                              void* d_out, int out_size) {
    const float* logits = (const float*)d_in[0];   // [512, 32768]
    const float* latlon = (const float*)d_in[1];   // [512, 2]
    const float* geo    = (const float*)d_in[2];   // [32768, 2]

    precompute<<<(C_CELLS + 255) / 256, 256>>>(geo, latlon);
    main_kernel<<<GRID, THREADS>>>(logits, (float*)d_out);
}